// round 7
// baseline (speedup 1.0000x reference)
#include <cuda_runtime.h>
#include <cuda_bf16.h>
#include <cstdint>

#define CORES   512
#define SLOTS   4
#define SLEN    64
#define PER_CORE (SLOTS * SLEN)          // 256
#define NSLOTS  (CORES * SLOTS)          // 2048 slots per layer
#define VEC_N   (CORES * PER_CORE)       // 131072
#define C_ENTRIES (CORES * SLOTS * CORES * SLOTS)
#define LIST_CAP 8
#define GRID_MV 592                      // 148 SMs x 4 CTAs (one full wave)
#define MV_TASKS (VEC_N / 4)             // 32768 4-row warp tasks per layer
#define GW_STRIDE (GRID_MV * 8)          // 4736 warps

// Scratch (__device__ globals; no allocation allowed)
__device__ float g_h[VEC_N];
__device__ float g_y1[VEC_N];
__device__ int   g_cnt[2 * NSLOTS];
__device__ int2  g_list[2 * NSLOTS * LIST_CAP];

// ---------------------------------------------------------------------------
__global__ void zero_cnt_kernel(int* __restrict__ cnt) {
    int i = blockIdx.x * blockDim.x + threadIdx.x;
    if (i < 2 * NSLOTS) cnt[i] = 0;
}

// ---------------------------------------------------------------------------
// Compact both routing tensors in one launch.
// C layout [I,J,K,L]: q = ij*512 + k indexes a float4 over l.
// ---------------------------------------------------------------------------
__global__ void compact_kernel(const float4* __restrict__ C1,
                               const float4* __restrict__ C2,
                               int* __restrict__ cnt,
                               int2* __restrict__ lst) {
    const int n4 = C_ENTRIES / 4;           // per tensor
    int g = blockIdx.x * blockDim.x + threadIdx.x;
    int half = gridDim.x * blockDim.x / 2;
    const float4* C = (g < half) ? C1 : C2;
    int* cn  = (g < half) ? cnt : cnt + NSLOTS;
    int2* ls = (g < half) ? lst : lst + NSLOTS * LIST_CAP;
    int base = (g < half) ? g : g - half;
    int stride = half;
    for (int q = base; q < n4; q += stride) {
        float4 v = __ldcs(&C[q]);
        int ij = q >> 9;
        int k  = q & 511;
        float vals[4] = {v.x, v.y, v.z, v.w};
#pragma unroll
        for (int l = 0; l < 4; l++) {
            if (vals[l] != 0.0f) {
                int s = k * 4 + l;
                int pos = atomicAdd(&cn[s], 1);
                if (pos < LIST_CAP)
                    ls[s * LIST_CAP + pos] = make_int2(ij, __float_as_int(vals[l]));
            }
        }
    }
}

// ---------------------------------------------------------------------------
// Dispatch gather, vectorized: thread = (slot s, 4-elem chunk m4).
// h4[s*16+m4] = sum_e w_e * src4[src_e*16 + m4].  All loads L2-hot.
// ---------------------------------------------------------------------------
__global__ void gather_kernel(const int* __restrict__ cnt,
                              const int2* __restrict__ lst,
                              const float4* __restrict__ src4,
                              float4* __restrict__ h4) {
    int idx = blockIdx.x * blockDim.x + threadIdx.x;   // 32768 threads
    int s  = idx >> 4;
    int m4 = idx & 15;
    int n = cnt[s];
    if (n > LIST_CAP) n = LIST_CAP;
    float ax = 0.f, ay = 0.f, az = 0.f, aw = 0.f;
#pragma unroll 4
    for (int e = 0; e < n; e++) {
        int2 ent = lst[s * LIST_CAP + e];
        float w = __int_as_float(ent.y);
        float4 v = src4[ent.x * 16 + m4];
        ax += w * v.x; ay += w * v.y; az += w * v.z; aw += w * v.w;
    }
    h4[idx] = make_float4(ax, ay, az, aw);
}

// ---------------------------------------------------------------------------
// Barrier-free streaming matvec + capped ReLU.
// Warp-grid-stride over 4-row tasks: task t -> core = t>>6, rows (t&63)*4+sub.
// Lanes: sub = lane>>3 (row), lg = lane&7 (128B column chunk). Per task:
// 8 coalesced W LDG.128 (streaming) + 8 h LDG.128 (L1/L2-hot) -> FFMA ->
// 3-level shfl within 8-lane groups -> 4-lane coalesced store. No smem,
// no __syncthreads, no atomics: warps stream continuously.
// W per-core layout [j,k,l,m]: row r=(j,l) stride j:16384 l:64; col c=(k,m).
// ---------------------------------------------------------------------------
__global__ void __launch_bounds__(256, 4) mv_kernel(
        const float* __restrict__ W,
        const float* __restrict__ h,
        float* __restrict__ y) {
    const int warp = threadIdx.x >> 5, lane = threadIdx.x & 31;
    const int lg  = lane & 7;
    const int sub = lane >> 3;
    const int gw  = blockIdx.x * 8 + warp;

    for (int t = gw; t < MV_TASKS; t += GW_STRIDE) {
        const int core = t >> 6;
        const int r = ((t & 63) << 2) + sub;
        const int j = r >> 6, l = r & 63;
        const float* rb = W + ((size_t)core << 16) + (j << 14) + (l << 6);
        const float* hb = h + (core << 8);
        float acc0 = 0.f, acc1 = 0.f;
#pragma unroll
        for (int tt = 0; tt < 8; tt++) {
            const int c = 4 * lg + 32 * tt;
            float4 w  = __ldcs(reinterpret_cast<const float4*>(
                                   rb + ((c >> 6) << 12) + (c & 63)));
            float4 hv = *reinterpret_cast<const float4*>(hb + c);
            if (tt & 1) {
                acc1 += w.x * hv.x + w.y * hv.y + w.z * hv.z + w.w * hv.w;
            } else {
                acc0 += w.x * hv.x + w.y * hv.y + w.z * hv.z + w.w * hv.w;
            }
        }
        float acc = acc0 + acc1;
        acc += __shfl_xor_sync(0xffffffffu, acc, 1);
        acc += __shfl_xor_sync(0xffffffffu, acc, 2);
        acc += __shfl_xor_sync(0xffffffffu, acc, 4);
        if (lg == 0)
            y[(core << 8) + r] = fminf(fmaxf(acc, 0.0f), 10.0f);
    }
}

// ---------------------------------------------------------------------------
extern "C" void kernel_launch(void* const* d_in, const int* in_sizes, int n_in,
                              void* d_out, int out_size) {
    const float* x  = (const float*)d_in[0];
    const float* Wi = (const float*)d_in[1];
    const float* Wo = (const float*)d_in[2];
    const float* Ci = (const float*)d_in[3];
    const float* Cc = (const float*)d_in[4];
    float* out = (float*)d_out;

    float* h;   cudaGetSymbolAddress((void**)&h,   g_h);
    float* y1;  cudaGetSymbolAddress((void**)&y1,  g_y1);
    int*   cnt; cudaGetSymbolAddress((void**)&cnt, g_cnt);
    int2*  lst; cudaGetSymbolAddress((void**)&lst, g_list);

    zero_cnt_kernel<<<(2 * NSLOTS + 255) / 256, 256>>>(cnt);

    compact_kernel<<<4096, 256>>>((const float4*)Ci, (const float4*)Cc,
                                  cnt, lst);

    // Layer 1
    gather_kernel<<<128, 256>>>(cnt, lst, (const float4*)x, (float4*)h);
    mv_kernel<<<GRID_MV, 256>>>(Wi, h, y1);

    // Layer 2
    gather_kernel<<<128, 256>>>(cnt + NSLOTS, lst + NSLOTS * LIST_CAP,
                                (const float4*)y1, (float4*)h);
    mv_kernel<<<GRID_MV, 256>>>(Wo, h, out);
}

// round 8
// speedup vs baseline: 1.0669x; 1.0669x over previous
#include <cuda_runtime.h>
#include <cuda_bf16.h>
#include <cstdint>

#define CORES   512
#define SLOTS   4
#define SLEN    64
#define PER_CORE (SLOTS * SLEN)          // 256
#define NSLOTS  (CORES * SLOTS)          // 2048 slots per layer
#define VEC_N   (CORES * PER_CORE)       // 131072
#define C_ENTRIES (CORES * SLOTS * CORES * SLOTS)
#define LIST_CAP 8
#define GRID_MV 592                      // 148 SMs x 4 CTAs (one full wave)
#define MV_TASKS8 (VEC_N / 8)            // 16384 8-row warp tasks
#define GW_STRIDE (GRID_MV * 8)          // 4736 warps

// Scratch (__device__ globals; no allocation allowed)
__device__ float g_h[VEC_N];
__device__ float g_y1[VEC_N];
__device__ int   g_cnt[2 * NSLOTS];
__device__ int2  g_list[2 * NSLOTS * LIST_CAP];

// ---------------------------------------------------------------------------
// Compact both routing tensors in one launch.
// C layout [I,J,K,L]: q = ij*512 + k indexes a float4 over l.
// ---------------------------------------------------------------------------
__global__ void compact_kernel(const float4* __restrict__ C1,
                               const float4* __restrict__ C2,
                               int* __restrict__ cnt,
                               int2* __restrict__ lst) {
    const int n4 = C_ENTRIES / 4;           // per tensor
    int g = blockIdx.x * blockDim.x + threadIdx.x;
    int half = gridDim.x * blockDim.x / 2;
    const float4* C = (g < half) ? C1 : C2;
    int* cn  = (g < half) ? cnt : cnt + NSLOTS;
    int2* ls = (g < half) ? lst : lst + NSLOTS * LIST_CAP;
    int base = (g < half) ? g : g - half;
    int stride = half;
    for (int q = base; q < n4; q += stride) {
        float4 v = __ldcs(&C[q]);
        int ij = q >> 9;
        int k  = q & 511;
        float vals[4] = {v.x, v.y, v.z, v.w};
#pragma unroll
        for (int l = 0; l < 4; l++) {
            if (vals[l] != 0.0f) {
                int s = k * 4 + l;
                int pos = atomicAdd(&cn[s], 1);
                if (pos < LIST_CAP)
                    ls[s * LIST_CAP + pos] = make_int2(ij, __float_as_int(vals[l]));
            }
        }
    }
}

// ---------------------------------------------------------------------------
// Dispatch gather, vectorized: thread = (slot s, 4-elem chunk m4).
// h4[s*16+m4] = sum_e w_e * src4[src_e*16 + m4].  All loads L2-hot.
// ---------------------------------------------------------------------------
__global__ void gather_kernel(const int* __restrict__ cnt,
                              const int2* __restrict__ lst,
                              const float4* __restrict__ src4,
                              float4* __restrict__ h4) {
    int idx = blockIdx.x * blockDim.x + threadIdx.x;   // 32768 threads
    int s  = idx >> 4;
    int m4 = idx & 15;
    int n = cnt[s];
    if (n > LIST_CAP) n = LIST_CAP;
    float ax = 0.f, ay = 0.f, az = 0.f, aw = 0.f;
#pragma unroll 4
    for (int e = 0; e < n; e++) {
        int2 ent = lst[s * LIST_CAP + e];
        float w = __int_as_float(ent.y);
        float4 v = src4[ent.x * 16 + m4];
        ax += w * v.x; ay += w * v.y; az += w * v.z; aw += w * v.w;
    }
    h4[idx] = make_float4(ax, ay, az, aw);
}

// ---------------------------------------------------------------------------
// Barrier-free streaming matvec + capped ReLU, 8-row warp tasks.
// Task t: core = t>>5, row group rg = t&31 covers rows rg*8 .. rg*8+7.
// Lanes: sub = lane>>3 (row within 4-group), lg = lane&7 (128B col chunk).
// Per task: 8 h LDG.128 (L1-hot, shared by both row halves) + 16 W LDG.128
// (streaming, two independent rows r0/r0+4 per lane) -> two acc chains ->
// interleaved 3-level shfl reduce -> coalesced stores. No smem/barriers.
// W per-core layout [j,k,l,m]: row r=(j,l) stride j:16384 l:64; col c=(k,m).
// ---------------------------------------------------------------------------
__global__ void __launch_bounds__(256, 4) mv_kernel(
        const float* __restrict__ W,
        const float* __restrict__ h,
        float* __restrict__ y) {
    const int warp = threadIdx.x >> 5, lane = threadIdx.x & 31;
    const int lg  = lane & 7;
    const int sub = lane >> 3;
    const int gw  = blockIdx.x * 8 + warp;

    for (int t = gw; t < MV_TASKS8; t += GW_STRIDE) {
        const int core = t >> 5;
        const int rg   = t & 31;
        const int r0 = (rg << 3) + sub;       // rows r0 and r0+4
        const int r1 = r0 + 4;
        const float* hb = h + (core << 8);

        float4 hv[8];
#pragma unroll
        for (int tt = 0; tt < 8; tt++)
            hv[tt] = *reinterpret_cast<const float4*>(hb + 4 * lg + 32 * tt);

        const float* Wc = W + ((size_t)core << 16);
        const float* rb0 = Wc + ((r0 >> 6) << 14) + ((r0 & 63) << 6);
        const float* rb1 = Wc + ((r1 >> 6) << 14) + ((r1 & 63) << 6);

        float a0 = 0.f, a1 = 0.f;
#pragma unroll
        for (int tt = 0; tt < 8; tt++) {
            const int c = 4 * lg + 32 * tt;
            const int off = ((c >> 6) << 12) + (c & 63);
            float4 w0 = __ldcs(reinterpret_cast<const float4*>(rb0 + off));
            float4 w1 = __ldcs(reinterpret_cast<const float4*>(rb1 + off));
            a0 += w0.x * hv[tt].x + w0.y * hv[tt].y + w0.z * hv[tt].z + w0.w * hv[tt].w;
            a1 += w1.x * hv[tt].x + w1.y * hv[tt].y + w1.z * hv[tt].z + w1.w * hv[tt].w;
        }
        a0 += __shfl_xor_sync(0xffffffffu, a0, 1);
        a1 += __shfl_xor_sync(0xffffffffu, a1, 1);
        a0 += __shfl_xor_sync(0xffffffffu, a0, 2);
        a1 += __shfl_xor_sync(0xffffffffu, a1, 2);
        a0 += __shfl_xor_sync(0xffffffffu, a0, 4);
        a1 += __shfl_xor_sync(0xffffffffu, a1, 4);
        if (lg == 0) {
            y[(core << 8) + r0] = fminf(fmaxf(a0, 0.0f), 10.0f);
            y[(core << 8) + r1] = fminf(fmaxf(a1, 0.0f), 10.0f);
        }
    }
}

// ---------------------------------------------------------------------------
extern "C" void kernel_launch(void* const* d_in, const int* in_sizes, int n_in,
                              void* d_out, int out_size) {
    const float* x  = (const float*)d_in[0];
    const float* Wi = (const float*)d_in[1];
    const float* Wo = (const float*)d_in[2];
    const float* Ci = (const float*)d_in[3];
    const float* Cc = (const float*)d_in[4];
    float* out = (float*)d_out;

    float* h;   cudaGetSymbolAddress((void**)&h,   g_h);
    float* y1;  cudaGetSymbolAddress((void**)&y1,  g_y1);
    int*   cnt; cudaGetSymbolAddress((void**)&cnt, g_cnt);
    int2*  lst; cudaGetSymbolAddress((void**)&lst, g_list);

    // Counter reset as a memset node (no kernel launch)
    cudaMemsetAsync(cnt, 0, 2 * NSLOTS * sizeof(int));

    compact_kernel<<<4096, 256>>>((const float4*)Ci, (const float4*)Cc,
                                  cnt, lst);

    // Layer 1
    gather_kernel<<<256, 128>>>(cnt, lst, (const float4*)x, (float4*)h);
    mv_kernel<<<GRID_MV, 256>>>(Wi, h, y1);

    // Layer 2
    gather_kernel<<<256, 128>>>(cnt + NSLOTS, lst + NSLOTS * LIST_CAP,
                                (const float4*)y1, (float4*)h);
    mv_kernel<<<GRID_MV, 256>>>(Wo, h, out);
}

// round 9
// speedup vs baseline: 1.1460x; 1.0741x over previous
#include <cuda_runtime.h>
#include <cuda_bf16.h>
#include <cstdint>

#define CORES   512
#define SLOTS   4
#define SLEN    64
#define PER_CORE (SLOTS * SLEN)          // 256
#define NSLOTS  (CORES * SLOTS)          // 2048 slots per layer
#define VEC_N   (CORES * PER_CORE)       // 131072
#define C_ENTRIES (CORES * SLOTS * CORES * SLOTS)
#define LIST_CAP 4                       // each slot has <=4 sources (slots=4 samples)
#define GRID_MV 592                      // 148 SMs x 4 CTAs (one full wave)
#define MV_TASKS8 (VEC_N / 8)            // 16384 8-row warp tasks
#define GW_STRIDE (GRID_MV * 8)          // 4736 warps

// Scratch packed so one memset node clears counters + list padding.
struct Scratch {
    int  cnt[2 * NSLOTS];
    int2 lst[2 * NSLOTS * LIST_CAP];     // zero entry = (src 0, weight 0.0f)
};
__device__ Scratch g_s;
__device__ float g_h[VEC_N];
__device__ float g_y1[VEC_N];

// ---------------------------------------------------------------------------
// Compact both routing tensors in one launch.
// C layout [I,J,K,L]: q = ij*512 + k indexes a float4 over l.
// ---------------------------------------------------------------------------
__global__ void compact_kernel(const float4* __restrict__ C1,
                               const float4* __restrict__ C2,
                               int* __restrict__ cnt,
                               int2* __restrict__ lst) {
    const int n4 = C_ENTRIES / 4;           // per tensor
    int g = blockIdx.x * blockDim.x + threadIdx.x;
    int half = gridDim.x * blockDim.x / 2;
    const float4* C = (g < half) ? C1 : C2;
    int* cn  = (g < half) ? cnt : cnt + NSLOTS;
    int2* ls = (g < half) ? lst : lst + NSLOTS * LIST_CAP;
    int base = (g < half) ? g : g - half;
    int stride = half;
    for (int q = base; q < n4; q += stride) {
        float4 v = __ldcs(&C[q]);
        int ij = q >> 9;
        int k  = q & 511;
        float vals[4] = {v.x, v.y, v.z, v.w};
#pragma unroll
        for (int l = 0; l < 4; l++) {
            if (vals[l] != 0.0f) {
                int s = k * 4 + l;
                int pos = atomicAdd(&cn[s], 1);
                if (pos < LIST_CAP)
                    ls[s * LIST_CAP + pos] = make_int2(ij, __float_as_int(vals[l]));
            }
        }
    }
}

// ---------------------------------------------------------------------------
// Dispatch gather, count-free: every slot processes exactly 4 (src, w)
// entries; padding entries have w = 0.0f and src = 0 (safe read).
// Thread = (slot s, 4-elem chunk m4). Chain depth 2: list int4 x2 -> src x4.
// ---------------------------------------------------------------------------
__global__ void gather_kernel(const int2* __restrict__ lst,
                              const float4* __restrict__ src4,
                              float4* __restrict__ h4) {
    int idx = blockIdx.x * blockDim.x + threadIdx.x;   // 32768 threads
    int s  = idx >> 4;
    int m4 = idx & 15;
    const int4* lp = reinterpret_cast<const int4*>(lst + s * LIST_CAP);
    int4 e01 = lp[0];   // (src0, w0, src1, w1)
    int4 e23 = lp[1];   // (src2, w2, src3, w3)
    float4 v0 = src4[e01.x * 16 + m4];
    float4 v1 = src4[e01.z * 16 + m4];
    float4 v2 = src4[e23.x * 16 + m4];
    float4 v3 = src4[e23.z * 16 + m4];
    float w0 = __int_as_float(e01.y), w1 = __int_as_float(e01.w);
    float w2 = __int_as_float(e23.y), w3 = __int_as_float(e23.w);
    float4 r;
    r.x = w0 * v0.x + w1 * v1.x + w2 * v2.x + w3 * v3.x;
    r.y = w0 * v0.y + w1 * v1.y + w2 * v2.y + w3 * v3.y;
    r.z = w0 * v0.z + w1 * v1.z + w2 * v2.z + w3 * v3.z;
    r.w = w0 * v0.w + w1 * v1.w + w2 * v2.w + w3 * v3.w;
    h4[idx] = r;
}

// ---------------------------------------------------------------------------
// Barrier-free streaming matvec + capped ReLU, 8-row warp tasks. (unchanged)
// W per-core layout [j,k,l,m]: row r=(j,l) stride j:16384 l:64; col c=(k,m).
// ---------------------------------------------------------------------------
__global__ void __launch_bounds__(256, 4) mv_kernel(
        const float* __restrict__ W,
        const float* __restrict__ h,
        float* __restrict__ y) {
    const int warp = threadIdx.x >> 5, lane = threadIdx.x & 31;
    const int lg  = lane & 7;
    const int sub = lane >> 3;
    const int gw  = blockIdx.x * 8 + warp;

    for (int t = gw; t < MV_TASKS8; t += GW_STRIDE) {
        const int core = t >> 5;
        const int rg   = t & 31;
        const int r0 = (rg << 3) + sub;       // rows r0 and r0+4
        const int r1 = r0 + 4;
        const float* hb = h + (core << 8);

        float4 hv[8];
#pragma unroll
        for (int tt = 0; tt < 8; tt++)
            hv[tt] = *reinterpret_cast<const float4*>(hb + 4 * lg + 32 * tt);

        const float* Wc = W + ((size_t)core << 16);
        const float* rb0 = Wc + ((r0 >> 6) << 14) + ((r0 & 63) << 6);
        const float* rb1 = Wc + ((r1 >> 6) << 14) + ((r1 & 63) << 6);

        float a0 = 0.f, a1 = 0.f;
#pragma unroll
        for (int tt = 0; tt < 8; tt++) {
            const int c = 4 * lg + 32 * tt;
            const int off = ((c >> 6) << 12) + (c & 63);
            float4 w0 = __ldcs(reinterpret_cast<const float4*>(rb0 + off));
            float4 w1 = __ldcs(reinterpret_cast<const float4*>(rb1 + off));
            a0 += w0.x * hv[tt].x + w0.y * hv[tt].y + w0.z * hv[tt].z + w0.w * hv[tt].w;
            a1 += w1.x * hv[tt].x + w1.y * hv[tt].y + w1.z * hv[tt].z + w1.w * hv[tt].w;
        }
        a0 += __shfl_xor_sync(0xffffffffu, a0, 1);
        a1 += __shfl_xor_sync(0xffffffffu, a1, 1);
        a0 += __shfl_xor_sync(0xffffffffu, a0, 2);
        a1 += __shfl_xor_sync(0xffffffffu, a1, 2);
        a0 += __shfl_xor_sync(0xffffffffu, a0, 4);
        a1 += __shfl_xor_sync(0xffffffffu, a1, 4);
        if (lg == 0) {
            y[(core << 8) + r0] = fminf(fmaxf(a0, 0.0f), 10.0f);
            y[(core << 8) + r1] = fminf(fmaxf(a1, 0.0f), 10.0f);
        }
    }
}

// ---------------------------------------------------------------------------
extern "C" void kernel_launch(void* const* d_in, const int* in_sizes, int n_in,
                              void* d_out, int out_size) {
    const float* x  = (const float*)d_in[0];
    const float* Wi = (const float*)d_in[1];
    const float* Wo = (const float*)d_in[2];
    const float* Ci = (const float*)d_in[3];
    const float* Cc = (const float*)d_in[4];
    float* out = (float*)d_out;

    Scratch* s; cudaGetSymbolAddress((void**)&s, g_s);
    float* h;   cudaGetSymbolAddress((void**)&h,   g_h);
    float* y1;  cudaGetSymbolAddress((void**)&y1,  g_y1);

    int*  cnt = s->cnt;
    int2* lst = s->lst;

    // One memset clears counters AND list padding (zero = src 0, weight 0.0f)
    cudaMemsetAsync(s, 0, sizeof(Scratch));

    compact_kernel<<<4096, 256>>>((const float4*)Ci, (const float4*)Cc,
                                  cnt, lst);

    // Layer 1
    gather_kernel<<<256, 128>>>(lst, (const float4*)x, (float4*)h);
    mv_kernel<<<GRID_MV, 256>>>(Wi, h, y1);

    // Layer 2
    gather_kernel<<<256, 128>>>(lst + NSLOTS * LIST_CAP,
                                (const float4*)y1, (float4*)h);
    mv_kernel<<<GRID_MV, 256>>>(Wo, h, out);
}